// round 1
// baseline (speedup 1.0000x reference)
#include <cuda_runtime.h>
#include <cstdint>
#include <cstddef>

#define B_    8
#define T_    8192
#define D_    512
#define H_    4
#define P_    24
#define HD_   128
#define TOPK_ 12
#define NC_   16      // token chunks per (b,h)
#define CHUNK_ 512    // tokens per chunk

// ---------------- scratch (static device globals; no allocation) ----------------
__device__ float g_xn[(size_t)B_ * T_ * D_];   // layernormed x
__device__ float g_K [(size_t)B_ * T_ * D_];   // K projection
__device__ float g_V [(size_t)B_ * T_ * D_];   // V projection
__device__ float g_Qh[H_ * P_ * HD_];          // normalized proto queries
__device__ float g_part[(size_t)B_ * H_ * NC_ * P_ * 130]; // per-chunk m,l,acc[128]
__device__ float g_pt[B_ * P_ * D_];           // proto_tokens [b][p][d]
__device__ float g_z [B_ * D_];
__device__ float g_hid[B_ * D_];

// ---------------- packed fp32 FMA (2 FMA / instr on Blackwell) ----------------
union F2U { float2 f; unsigned long long u; };
__device__ __forceinline__ void ffma2(float2& c, float2 a, float2 b) {
    F2U uc, ua, ub; uc.f = c; ua.f = a; ub.f = b;
    asm("fma.rn.f32x2 %0, %1, %2, %0;" : "+l"(uc.u) : "l"(ua.u), "l"(ub.u));
    c = uc.f;
}

// ---------------- 1. LayerNorm: one warp per token row ----------------
__global__ __launch_bounds__(256) void ln_kernel(const float* __restrict__ x,
                                                 const float* __restrict__ gw,
                                                 const float* __restrict__ bw) {
    int lane = threadIdx.x & 31;
    size_t row = (size_t)blockIdx.x * 8 + (threadIdx.x >> 5);
    const float* xr = x + row * D_;
    float4 v[4];
    float s = 0.f, sq = 0.f;
#pragma unroll
    for (int j = 0; j < 4; j++) {
        v[j] = *(const float4*)&xr[lane * 4 + j * 128];
        s  += v[j].x + v[j].y + v[j].z + v[j].w;
        sq += v[j].x * v[j].x + v[j].y * v[j].y + v[j].z * v[j].z + v[j].w * v[j].w;
    }
#pragma unroll
    for (int o = 16; o > 0; o >>= 1) {
        s  += __shfl_xor_sync(0xffffffffu, s,  o);
        sq += __shfl_xor_sync(0xffffffffu, sq, o);
    }
    float mu   = s * (1.f / 512.f);
    float var  = sq * (1.f / 512.f) - mu * mu;
    float rstd = rsqrtf(var + 1e-5f);
    float* orow = g_xn + row * D_;
#pragma unroll
    for (int j = 0; j < 4; j++) {
        int c = lane * 4 + j * 128;
        float4 gv = *(const float4*)&gw[c];
        float4 bv = *(const float4*)&bw[c];
        float4 o;
        o.x = (v[j].x - mu) * rstd * gv.x + bv.x;
        o.y = (v[j].y - mu) * rstd * gv.y + bv.y;
        o.z = (v[j].z - mu) * rstd * gv.z + bv.z;
        o.w = (v[j].w - mu) * rstd * gv.w + bv.w;
        *(float4*)&orow[c] = o;
    }
}

// ---------------- 2. GEMM: C[M,512] = g_xn[M,512] @ W[512,512]^T ----------------
// 128x128 block tile, BK=16, 256 threads, 8x8 microtile, double-buffered smem,
// packed f32x2 FMAs. which==0 -> g_K, which==1 -> g_V.
__global__ __launch_bounds__(256, 2) void gemm_nt(const float* __restrict__ W, int which) {
    const float* A = g_xn;
    float* C = which ? g_V : g_K;
    __shared__ float As[2][16][128];
    __shared__ float Bs[2][16][128];
    int tid = threadIdx.x;
    size_t m0 = (size_t)blockIdx.x * 128;
    int n0 = blockIdx.y * 128;
    int tx = tid & 15, ty = tid >> 4;
    int lr = tid >> 2, lc = tid & 3;

    float2 acc[8][4];
#pragma unroll
    for (int r = 0; r < 8; r++)
#pragma unroll
        for (int j = 0; j < 4; j++) acc[r][j] = make_float2(0.f, 0.f);

    const float* Ab0 = A + (m0 + lr) * 512 + lc * 4;
    const float* Ab1 = A + (m0 + lr + 64) * 512 + lc * 4;
    const float* Wb0 = W + (size_t)(n0 + lr) * 512 + lc * 4;
    const float* Wb1 = W + (size_t)(n0 + lr + 64) * 512 + lc * 4;

    auto sts_tile = [&](int bf, float4 a0, float4 a1, float4 b0, float4 b1) {
        As[bf][lc * 4 + 0][lr]      = a0.x; As[bf][lc * 4 + 1][lr]      = a0.y;
        As[bf][lc * 4 + 2][lr]      = a0.z; As[bf][lc * 4 + 3][lr]      = a0.w;
        As[bf][lc * 4 + 0][lr + 64] = a1.x; As[bf][lc * 4 + 1][lr + 64] = a1.y;
        As[bf][lc * 4 + 2][lr + 64] = a1.z; As[bf][lc * 4 + 3][lr + 64] = a1.w;
        Bs[bf][lc * 4 + 0][lr]      = b0.x; Bs[bf][lc * 4 + 1][lr]      = b0.y;
        Bs[bf][lc * 4 + 2][lr]      = b0.z; Bs[bf][lc * 4 + 3][lr]      = b0.w;
        Bs[bf][lc * 4 + 0][lr + 64] = b1.x; Bs[bf][lc * 4 + 1][lr + 64] = b1.y;
        Bs[bf][lc * 4 + 2][lr + 64] = b1.z; Bs[bf][lc * 4 + 3][lr + 64] = b1.w;
    };

    {
        float4 a0 = *(const float4*)Ab0;
        float4 a1 = *(const float4*)Ab1;
        float4 b0 = *(const float4*)Wb0;
        float4 b1 = *(const float4*)Wb1;
        sts_tile(0, a0, a1, b0, b1);
    }
    __syncthreads();

    int buf = 0;
    float4 pa0, pa1, pb0, pb1;
#pragma unroll 1
    for (int kt = 0; kt < 32; ++kt) {
        if (kt < 31) {
            int ko = (kt + 1) * 16;
            pa0 = *(const float4*)(Ab0 + ko);
            pa1 = *(const float4*)(Ab1 + ko);
            pb0 = *(const float4*)(Wb0 + ko);
            pb1 = *(const float4*)(Wb1 + ko);
        }
#pragma unroll
        for (int k = 0; k < 16; k++) {
            float4 a0 = *(const float4*)&As[buf][k][ty * 8];
            float4 a1 = *(const float4*)&As[buf][k][ty * 8 + 4];
            float4 b0 = *(const float4*)&Bs[buf][k][tx * 8];
            float4 b1 = *(const float4*)&Bs[buf][k][tx * 8 + 4];
            float ar[8] = {a0.x, a0.y, a0.z, a0.w, a1.x, a1.y, a1.z, a1.w};
            float2 br[4] = {{b0.x, b0.y}, {b0.z, b0.w}, {b1.x, b1.y}, {b1.z, b1.w}};
#pragma unroll
            for (int r = 0; r < 8; r++) {
                float2 a2 = make_float2(ar[r], ar[r]);
#pragma unroll
                for (int j = 0; j < 4; j++) ffma2(acc[r][j], a2, br[j]);
            }
        }
        if (kt < 31) {
            int nb = buf ^ 1;
            sts_tile(nb, pa0, pa1, pb0, pb1);
            __syncthreads();
            buf = nb;
        }
    }
#pragma unroll
    for (int r = 0; r < 8; r++) {
        float4 o0 = make_float4(acc[r][0].x, acc[r][0].y, acc[r][1].x, acc[r][1].y);
        float4 o1 = make_float4(acc[r][2].x, acc[r][2].y, acc[r][3].x, acc[r][3].y);
        float* cp = C + (m0 + ty * 8 + r) * 512 + n0 + tx * 8;
        *(float4*)cp       = o0;
        *(float4*)(cp + 4) = o1;
    }
}

// ---------------- 3. Qh = l2norm per head of (proto @ Wq^T) ----------------
__global__ __launch_bounds__(128) void qh_kernel(const float* __restrict__ proto,
                                                 const float* __restrict__ Wq) {
    __shared__ float pr[D_];
    __shared__ float qp[D_];
    int p = blockIdx.x, tid = threadIdx.x;
    for (int i = tid; i < D_; i += 128) pr[i] = proto[p * D_ + i];
    __syncthreads();
#pragma unroll
    for (int jj = 0; jj < 4; jj++) {
        int n = tid * 4 + jj;
        const float* wr = Wq + (size_t)n * D_;
        float a = 0.f;
        for (int k = 0; k < D_; k += 4) {
            float4 w4 = *(const float4*)&wr[k];
            a += w4.x * pr[k] + w4.y * pr[k + 1] + w4.z * pr[k + 2] + w4.w * pr[k + 3];
        }
        qp[n] = a;
    }
    __syncthreads();
    int w = tid >> 5, lane = tid & 31;      // warp w handles head w
    const float* qh = qp + w * HD_;
    float sq = 0.f;
#pragma unroll
    for (int j = 0; j < 4; j++) { float t = qh[lane + 32 * j]; sq += t * t; }
#pragma unroll
    for (int o = 16; o > 0; o >>= 1) sq += __shfl_xor_sync(0xffffffffu, sq, o);
    float inv = 1.f / fmaxf(sqrtf(sq), 1e-12f);
#pragma unroll
    for (int j = 0; j < 4; j++) {
        int d = lane + 32 * j;
        g_Qh[(w * P_ + p) * HD_ + d] = qh[d] * inv;
    }
}

// ---------------- 4. attention partials (flash-style, per 512-token chunk) ----------------
// grid (NC_, H_, B_), 256 threads, dynamic smem 94400 B.
__global__ __launch_bounds__(256) void att_kernel() {
    extern __shared__ float sm[];
    float* Qs = sm;                 // 24*128
    float* Ss = sm + 3072;          // 24*512
    float* Vs = Ss + 12288;         // 64*128
    float* Ms = Vs + 8192;          // 24
    float* Ls = Ms + 24;            // 24
    int tid = threadIdx.x;
    int cz = blockIdx.x, h = blockIdx.y, b = blockIdx.z;

#pragma unroll
    for (int j = 0; j < 12; j++) {
        int i = tid + 256 * j;
        Qs[i] = g_Qh[h * (P_ * HD_) + i];
    }
    __syncthreads();

    // ---- scores: s[p,t] = dot(Qh[p], K[t]) / (max(|K[t]|,eps)*TEMP) ----
    for (int it = 0; it < 2; ++it) {
        int tl = tid + it * 256;
        const float4* kp = (const float4*)(g_K + ((size_t)(b * T_ + cz * CHUNK_ + tl)) * D_ + h * HD_);
        float acc[P_];
#pragma unroll
        for (int p = 0; p < P_; p++) acc[p] = 0.f;
        float nn = 0.f;
#pragma unroll 1
        for (int q = 0; q < 4; q++) {
            float kq[32];
#pragma unroll
            for (int i = 0; i < 8; i++) {
                float4 k4 = kp[q * 8 + i];
                kq[i * 4 + 0] = k4.x; kq[i * 4 + 1] = k4.y;
                kq[i * 4 + 2] = k4.z; kq[i * 4 + 3] = k4.w;
                nn += k4.x * k4.x + k4.y * k4.y + k4.z * k4.z + k4.w * k4.w;
            }
#pragma unroll
            for (int p = 0; p < P_; p++) {
                const float4* qr = (const float4*)&Qs[p * HD_ + q * 32];
                float a = 0.f;
#pragma unroll
                for (int i = 0; i < 8; i++) {
                    float4 q4 = qr[i];
                    a += q4.x * kq[i * 4] + q4.y * kq[i * 4 + 1] +
                         q4.z * kq[i * 4 + 2] + q4.w * kq[i * 4 + 3];
                }
                acc[p] += a;
            }
        }
        float inv = 1.f / (fmaxf(sqrtf(nn), 1e-12f) * 0.07f);
#pragma unroll
        for (int p = 0; p < P_; p++) Ss[p * CHUNK_ + tl] = acc[p] * inv;
    }
    __syncthreads();

    // ---- per-row chunk softmax stats; Ss <- exp(s - m) ----
    int w = tid >> 5, lane = tid & 31;
#pragma unroll 1
    for (int rr = 0; rr < 3; ++rr) {
        int p = w + rr * 8;
        float vals[16];
        float m = -3.4e38f;
#pragma unroll
        for (int j = 0; j < 16; j++) {
            vals[j] = Ss[p * CHUNK_ + lane + 32 * j];
            m = fmaxf(m, vals[j]);
        }
#pragma unroll
        for (int o = 16; o > 0; o >>= 1) m = fmaxf(m, __shfl_xor_sync(0xffffffffu, m, o));
        float s = 0.f;
#pragma unroll
        for (int j = 0; j < 16; j++) {
            float e = expf(vals[j] - m);
            Ss[p * CHUNK_ + lane + 32 * j] = e;
            s += e;
        }
#pragma unroll
        for (int o = 16; o > 0; o >>= 1) s += __shfl_xor_sync(0xffffffffu, s, o);
        if (lane == 0) { Ms[p] = m; Ls[p] = s; }
    }

    // ---- PV: acc[p][d] = sum_t exp(s)*V ; thread owns (p-group of 6, dim-pair) ----
    int pg = tid >> 6;      // 0..3 -> 6 protos each
    int d2 = tid & 63;      // dim pair
    float2 acc6[6];
#pragma unroll
    for (int j = 0; j < 6; j++) acc6[j] = make_float2(0.f, 0.f);
    const float2* Vs2 = (const float2*)Vs;
#pragma unroll 1
    for (int st = 0; st < 8; ++st) {
        __syncthreads();
#pragma unroll
        for (int j = 0; j < 8; j++) {
            int lin = tid + 256 * j;
            int row = lin >> 5, c4 = lin & 31;
            float4 vv = *(const float4*)&g_V[((size_t)(b * T_ + cz * CHUNK_ + st * 64 + row)) * D_ + h * HD_ + c4 * 4];
            *(float4*)&Vs[row * HD_ + c4 * 4] = vv;
        }
        __syncthreads();
#pragma unroll 4
        for (int t = 0; t < 64; t++) {
            float2 v = Vs2[t * 64 + d2];
            int tt = st * 64 + t;
#pragma unroll
            for (int j = 0; j < 6; j++) {
                float sv = Ss[(pg * 6 + j) * CHUNK_ + tt];
                acc6[j].x += sv * v.x;
                acc6[j].y += sv * v.y;
            }
        }
    }
    size_t pb = ((((size_t)b * H_ + h) * NC_ + cz) * P_) * 130;
#pragma unroll
    for (int j = 0; j < 6; j++) {
        int p = pg * 6 + j;
        float* dst = g_part + pb + (size_t)p * 130;
        *(float2*)&dst[2 + 2 * d2] = acc6[j];
        if (d2 == 0) { dst[0] = Ms[p]; dst[1] = Ls[p]; }
    }
}

// ---------------- 5. merge chunk partials -> proto_tokens ----------------
__global__ __launch_bounds__(128) void merge_kernel() {
    int p = blockIdx.x, h = blockIdx.y, b = blockIdx.z;
    int d = threadIdx.x;
    float M = -3.4e38f;
    for (int c = 0; c < NC_; c++) {
        const float* pp = g_part + (((size_t)(b * H_ + h) * NC_ + c) * P_ + p) * 130;
        M = fmaxf(M, pp[0]);
    }
    float L = 0.f, val = 0.f;
    for (int c = 0; c < NC_; c++) {
        const float* pp = g_part + (((size_t)(b * H_ + h) * NC_ + c) * P_ + p) * 130;
        float wgt = expf(pp[0] - M);
        L   += pp[1] * wgt;
        val += pp[2 + d] * wgt;
    }
    float out = (L > 0.f) ? val / L : 0.f;   // nan_to_num guard
    g_pt[(b * P_ + p) * D_ + h * HD_ + d] = out;
}

// ---------------- 6. proto scores, top-k, mean -> z ----------------
__global__ __launch_bounds__(256) void topk_kernel() {
    int b = blockIdx.x, tid = threadIdx.x, w = tid >> 5, lane = tid & 31;
    __shared__ float ss[P_];
    __shared__ int idxs[TOPK_];
#pragma unroll 1
    for (int rr = 0; rr < 3; rr++) {
        int p = w + rr * 8;
        const float* pr = g_pt + (b * P_ + p) * D_;
        float sq = 0.f;
#pragma unroll
        for (int j = 0; j < 16; j++) { float t = pr[lane + 32 * j]; sq += t * t; }
#pragma unroll
        for (int o = 16; o > 0; o >>= 1) sq += __shfl_xor_sync(0xffffffffu, sq, o);
        if (lane == 0) ss[p] = sq;
    }
    __syncthreads();
    if (tid == 0) {
        unsigned used = 0;
        for (int i = 0; i < TOPK_; i++) {
            int best = -1; float bv = -3.4e38f;
            for (int p = 0; p < P_; p++)
                if (!((used >> p) & 1) && ss[p] > bv) { bv = ss[p]; best = p; }
            used |= 1u << best;
            idxs[i] = best;
        }
    }
    __syncthreads();
    for (int d = tid; d < D_; d += 256) {
        float s = 0.f;
        for (int i = 0; i < TOPK_; i++) s += g_pt[(b * P_ + idxs[i]) * D_ + d];
        g_z[b * D_ + d] = s * (1.f / TOPK_);
    }
}

// ---------------- 7. MLP layers (GEMV) ----------------
__global__ __launch_bounds__(128) void mlp_kernel(int in_sel, const float* __restrict__ W,
                                                  const float* __restrict__ bias,
                                                  float* __restrict__ out_ext, int act) {
    __shared__ float zs[D_];
    int b = blockIdx.y, tid = threadIdx.x;
    int n = blockIdx.x * 128 + tid;
    const float* in = in_sel ? g_hid : g_z;
    for (int i = tid; i < D_; i += 128) zs[i] = in[b * D_ + i];
    __syncthreads();
    const float* wr = W + (size_t)n * D_;
    float s = bias[n];
    for (int k = 0; k < D_; k += 4) {
        float4 w4 = *(const float4*)&wr[k];
        s += w4.x * zs[k] + w4.y * zs[k + 1] + w4.z * zs[k + 2] + w4.w * zs[k + 3];
    }
    if (act) s = s / (1.f + expf(-s));      // silu
    float* out = out_ext ? out_ext : g_hid;
    out[b * D_ + n] = s;
}

// ---------------- launch ----------------
extern "C" void kernel_launch(void* const* d_in, const int* in_sizes, int n_in,
                              void* d_out, int out_size) {
    (void)in_sizes; (void)n_in; (void)out_size;
    const float* x     = (const float*)d_in[0];
    const float* proto = (const float*)d_in[1];
    const float* ln_g  = (const float*)d_in[2];
    const float* ln_b  = (const float*)d_in[3];
    const float* Wq    = (const float*)d_in[4];
    const float* Wk    = (const float*)d_in[5];
    const float* Wv    = (const float*)d_in[6];
    const float* W1    = (const float*)d_in[7];
    const float* b1    = (const float*)d_in[8];
    const float* W2    = (const float*)d_in[9];
    const float* b2    = (const float*)d_in[10];
    float* out = (float*)d_out;

    ln_kernel<<<(B_ * T_) / 8, 256>>>(x, ln_g, ln_b);
    gemm_nt<<<dim3((B_ * T_) / 128, 4), 256>>>(Wk, 0);
    gemm_nt<<<dim3((B_ * T_) / 128, 4), 256>>>(Wv, 1);
    qh_kernel<<<P_, 128>>>(proto, Wq);

    static int smem_set = 0;
    // setting the attribute every call is idempotent and capture-safe
    cudaFuncSetAttribute(att_kernel, cudaFuncAttributeMaxDynamicSharedMemorySize, 94400);
    (void)smem_set;
    att_kernel<<<dim3(NC_, H_, B_), 256, 94400>>>();
    merge_kernel<<<dim3(P_, H_, B_), 128>>>();
    topk_kernel<<<B_, 256>>>();
    mlp_kernel<<<dim3(4, B_), 128>>>(0, W1, b1, nullptr, 1);
    mlp_kernel<<<dim3(4, B_), 128>>>(1, W2, b2, out, 0);
}

// round 4
// speedup vs baseline: 2.1066x; 2.1066x over previous
#include <cuda_runtime.h>
#include <cstdint>
#include <cstddef>

#define B_    8
#define T_    8192
#define D_    512
#define H_    4
#define P_    24
#define HD_   128
#define TOPK_ 12
#define NC_   16
#define CHUNK_ 512

// ---------------- scratch (static device globals; no allocation) ----------------
__device__ __align__(16) float g_xn[(size_t)B_ * T_ * D_];   // tf32-rounded LN output
__device__ __align__(16) float g_K [(size_t)B_ * T_ * D_];
__device__ __align__(16) float g_V [(size_t)B_ * T_ * D_];
__device__ __align__(16) float g_Wt[2 * D_ * D_];            // tf32-rounded Wk, Wv
__device__ float g_Qh[H_ * P_ * HD_];
__device__ float g_part[(size_t)B_ * H_ * NC_ * P_ * 130];
__device__ float g_pt[B_ * P_ * D_];
__device__ float g_z [B_ * D_];
__device__ float g_hid[B_ * D_];

// ---------------- helpers ----------------
__device__ __forceinline__ float tf32r(float v) {
    uint32_t o;
    asm("cvt.rna.tf32.f32 %0, %1;" : "=r"(o) : "f"(v));
    return __uint_as_float(o);
}
__device__ __forceinline__ uint32_t smem_u32(const void* p) {
    uint32_t a;
    asm("{ .reg .u64 t; cvta.to.shared.u64 t, %1; cvt.u32.u64 %0, t; }" : "=r"(a) : "l"(p));
    return a;
}
__device__ __forceinline__ void cp16(uint32_t s, const void* g) {
    asm volatile("cp.async.cg.shared.global [%0], [%1], 16;" :: "r"(s), "l"(g) : "memory");
}
__device__ __forceinline__ void cp_commit() {
    asm volatile("cp.async.commit_group;" ::: "memory");
}
template <int N> __device__ __forceinline__ void cp_wait() {
    asm volatile("cp.async.wait_group %0;" :: "n"(N) : "memory");
}
__device__ __forceinline__ void mma_tf32(float& c0, float& c1, float& c2, float& c3,
                                         uint32_t a0, uint32_t a1, uint32_t a2, uint32_t a3,
                                         uint32_t b0, uint32_t b1) {
    asm volatile("mma.sync.aligned.m16n8k8.row.col.f32.tf32.tf32.f32 "
                 "{%0,%1,%2,%3}, {%4,%5,%6,%7}, {%8,%9}, {%0,%1,%2,%3};"
                 : "+f"(c0), "+f"(c1), "+f"(c2), "+f"(c3)
                 : "r"(a0), "r"(a1), "r"(a2), "r"(a3), "r"(b0), "r"(b1));
}

// ---------------- 1. LayerNorm (writes tf32-rounded xn) ----------------
__global__ __launch_bounds__(256) void ln_kernel(const float* __restrict__ x,
                                                 const float* __restrict__ gw,
                                                 const float* __restrict__ bw) {
    int lane = threadIdx.x & 31;
    size_t row = (size_t)blockIdx.x * 8 + (threadIdx.x >> 5);
    const float* xr = x + row * D_;
    float4 v[4];
    float s = 0.f, sq = 0.f;
#pragma unroll
    for (int j = 0; j < 4; j++) {
        v[j] = *(const float4*)&xr[lane * 4 + j * 128];
        s  += v[j].x + v[j].y + v[j].z + v[j].w;
        sq += v[j].x * v[j].x + v[j].y * v[j].y + v[j].z * v[j].z + v[j].w * v[j].w;
    }
#pragma unroll
    for (int o = 16; o > 0; o >>= 1) {
        s  += __shfl_xor_sync(0xffffffffu, s,  o);
        sq += __shfl_xor_sync(0xffffffffu, sq, o);
    }
    float mu   = s * (1.f / 512.f);
    float var  = sq * (1.f / 512.f) - mu * mu;
    float rstd = rsqrtf(var + 1e-5f);
    float* orow = g_xn + row * D_;
#pragma unroll
    for (int j = 0; j < 4; j++) {
        int c = lane * 4 + j * 128;
        float4 gv = *(const float4*)&gw[c];
        float4 bv = *(const float4*)&bw[c];
        float4 o;
        o.x = tf32r((v[j].x - mu) * rstd * gv.x + bv.x);
        o.y = tf32r((v[j].y - mu) * rstd * gv.y + bv.y);
        o.z = tf32r((v[j].z - mu) * rstd * gv.z + bv.z);
        o.w = tf32r((v[j].w - mu) * rstd * gv.w + bv.w);
        *(float4*)&orow[c] = o;
    }
}

// ---------------- 1b. round W matrices to tf32 ----------------
__global__ __launch_bounds__(256) void round_w(const float* __restrict__ Wk,
                                               const float* __restrict__ Wv) {
    int i = blockIdx.x * 256 + threadIdx.x;
    g_Wt[i]             = tf32r(Wk[i]);
    g_Wt[D_ * D_ + i]   = tf32r(Wv[i]);
}

// ---------------- 2. tf32 mma.sync GEMM: C = xn @ W^T ----------------
// grid (8, 512): x = {which(2) x ntile(4)}, y = m tile. CTA 128x128x(K=512).
// 256 threads = 8 warps (2m x 4n), warp tile 64x32, m16n8k8 frags.
#define BK 32
#define ASTRIDE 36
#define BUF_FLOATS (128 * ASTRIDE)   // 4608

__global__ __launch_bounds__(256, 2) void gemm_mma() {
    extern __shared__ __align__(16) float sm[];
    float* As = sm;                       // [2][128][36]
    float* Ws = sm + 2 * BUF_FLOATS;
    const uint32_t smA = smem_u32(As);
    const uint32_t smW = smem_u32(Ws);

    const int tid = threadIdx.x;
    const int wid = tid >> 5, lane = tid & 31;
    const int which = blockIdx.x >> 2;
    const int n0 = (blockIdx.x & 3) * 128;
    const size_t m0 = (size_t)blockIdx.y * 128;
    const float* Wt = g_Wt + (size_t)which * (D_ * D_);
    float* C = which ? g_V : g_K;

    const int lrow = tid >> 1;            // 0..127
    const int lcb  = (tid & 1) * 16;      // 0 or 16
    const float* ga0 = g_xn + (m0 + lrow) * D_ + lcb;
    const float* gw0 = Wt + (size_t)(n0 + lrow) * D_ + lcb;
    const uint32_t sa0 = smA + (uint32_t)(lrow * ASTRIDE + lcb) * 4;
    const uint32_t sw0 = smW + (uint32_t)(lrow * ASTRIDE + lcb) * 4;

    const int wm = (wid >> 2) * 64;
    const int wn = (wid & 3) * 32;
    const int g  = lane >> 2;
    const int t  = lane & 3;

    float c[4][4][4];
#pragma unroll
    for (int mi = 0; mi < 4; mi++)
#pragma unroll
        for (int ni = 0; ni < 4; ni++)
#pragma unroll
            for (int j = 0; j < 4; j++) c[mi][ni][j] = 0.f;

    // prefetch k-tile 0 into buffer 0
#pragma unroll
    for (int j = 0; j < 4; j++) {
        cp16(sa0 + j * 16, ga0 + j * 4);
        cp16(sw0 + j * 16, gw0 + j * 4);
    }
    cp_commit();

    int buf = 0;
#pragma unroll 1
    for (int kt = 0; kt < 16; ++kt) {
        if (kt < 15) {
            int k0 = (kt + 1) * BK;
            int nb = buf ^ 1;
#pragma unroll
            for (int j = 0; j < 4; j++) {
                cp16(sa0 + (uint32_t)nb * BUF_FLOATS * 4 + j * 16, ga0 + k0 + j * 4);
                cp16(sw0 + (uint32_t)nb * BUF_FLOATS * 4 + j * 16, gw0 + k0 + j * 4);
            }
            cp_commit();
            cp_wait<1>();
        } else {
            cp_wait<0>();
        }
        __syncthreads();

        const float* Ab = As + buf * BUF_FLOATS;
        const float* Wb = Ws + buf * BUF_FLOATS;
#pragma unroll
        for (int ks = 0; ks < 4; ks++) {
            uint32_t a[4][4], bfr[4][2];
#pragma unroll
            for (int mi = 0; mi < 4; mi++) {
                const float* ap = Ab + (wm + mi * 16 + g) * ASTRIDE + ks * 8 + t;
                a[mi][0] = __float_as_uint(ap[0]);
                a[mi][1] = __float_as_uint(ap[8 * ASTRIDE]);
                a[mi][2] = __float_as_uint(ap[4]);
                a[mi][3] = __float_as_uint(ap[8 * ASTRIDE + 4]);
            }
#pragma unroll
            for (int ni = 0; ni < 4; ni++) {
                const float* bp = Wb + (wn + ni * 8 + g) * ASTRIDE + ks * 8 + t;
                bfr[ni][0] = __float_as_uint(bp[0]);
                bfr[ni][1] = __float_as_uint(bp[4]);
            }
#pragma unroll
            for (int mi = 0; mi < 4; mi++)
#pragma unroll
                for (int ni = 0; ni < 4; ni++)
                    mma_tf32(c[mi][ni][0], c[mi][ni][1], c[mi][ni][2], c[mi][ni][3],
                             a[mi][0], a[mi][1], a[mi][2], a[mi][3],
                             bfr[ni][0], bfr[ni][1]);
        }
        __syncthreads();
        buf ^= 1;
    }

#pragma unroll
    for (int mi = 0; mi < 4; mi++) {
#pragma unroll
        for (int ni = 0; ni < 4; ni++) {
            size_t r0 = m0 + wm + mi * 16 + g;
            int col = n0 + wn + ni * 8 + t * 2;
            *(float2*)&C[r0 * D_ + col]        = make_float2(c[mi][ni][0], c[mi][ni][1]);
            *(float2*)&C[(r0 + 8) * D_ + col]  = make_float2(c[mi][ni][2], c[mi][ni][3]);
        }
    }
}

// ---------------- 3. Qh ----------------
__global__ __launch_bounds__(512) void qh_kernel(const float* __restrict__ proto,
                                                 const float* __restrict__ Wq) {
    __shared__ float pr[D_];
    __shared__ float qp[D_];
    __shared__ float inv[H_];
    int p = blockIdx.x, tid = threadIdx.x;
    pr[tid] = proto[p * D_ + tid];
    __syncthreads();
    const float* wr = Wq + (size_t)tid * D_;
    float a = 0.f;
#pragma unroll 8
    for (int k = 0; k < D_; k += 4) {
        float4 w4 = *(const float4*)&wr[k];
        a += w4.x * pr[k] + w4.y * pr[k + 1] + w4.z * pr[k + 2] + w4.w * pr[k + 3];
    }
    qp[tid] = a;
    __syncthreads();
    int w = tid >> 5, lane = tid & 31;
    if (w < H_) {
        float sq = 0.f;
#pragma unroll
        for (int j = 0; j < 4; j++) { float tv = qp[w * HD_ + lane + 32 * j]; sq += tv * tv; }
#pragma unroll
        for (int o = 16; o > 0; o >>= 1) sq += __shfl_xor_sync(0xffffffffu, sq, o);
        if (lane == 0) inv[w] = 1.f / fmaxf(sqrtf(sq), 1e-12f);
    }
    __syncthreads();
    int hh = tid >> 7;
    g_Qh[(hh * P_ + p) * HD_ + (tid & 127)] = qp[tid] * inv[hh];
}

// ---------------- 4. attention partials ----------------
__global__ __launch_bounds__(256) void att_kernel() {
    extern __shared__ float smf[];
    float* Qs = smf;
    float* Ss = smf + 3072;
    float* Vs = Ss + 12288;
    float* Ms = Vs + 8192;
    float* Ls = Ms + 24;
    int tid = threadIdx.x;
    int cz = blockIdx.x, h = blockIdx.y, b = blockIdx.z;

#pragma unroll
    for (int j = 0; j < 12; j++) {
        int i = tid + 256 * j;
        Qs[i] = g_Qh[h * (P_ * HD_) + i];
    }
    __syncthreads();

    for (int it = 0; it < 2; ++it) {
        int tl = tid + it * 256;
        const float4* kp = (const float4*)(g_K + ((size_t)(b * T_ + cz * CHUNK_ + tl)) * D_ + h * HD_);
        float acc[P_];
#pragma unroll
        for (int p = 0; p < P_; p++) acc[p] = 0.f;
        float nn = 0.f;
#pragma unroll 1
        for (int q = 0; q < 4; q++) {
            float kq[32];
#pragma unroll
            for (int i = 0; i < 8; i++) {
                float4 k4 = kp[q * 8 + i];
                kq[i * 4 + 0] = k4.x; kq[i * 4 + 1] = k4.y;
                kq[i * 4 + 2] = k4.z; kq[i * 4 + 3] = k4.w;
                nn += k4.x * k4.x + k4.y * k4.y + k4.z * k4.z + k4.w * k4.w;
            }
#pragma unroll
            for (int p = 0; p < P_; p++) {
                const float4* qr = (const float4*)&Qs[p * HD_ + q * 32];
                float a = 0.f;
#pragma unroll
                for (int i = 0; i < 8; i++) {
                    float4 q4 = qr[i];
                    a += q4.x * kq[i * 4] + q4.y * kq[i * 4 + 1] +
                         q4.z * kq[i * 4 + 2] + q4.w * kq[i * 4 + 3];
                }
                acc[p] += a;
            }
        }
        float inv = 1.f / (fmaxf(sqrtf(nn), 1e-12f) * 0.07f);
#pragma unroll
        for (int p = 0; p < P_; p++) Ss[p * CHUNK_ + tl] = acc[p] * inv;
    }
    __syncthreads();

    int w = tid >> 5, lane = tid & 31;
#pragma unroll 1
    for (int rr = 0; rr < 3; ++rr) {
        int p = w + rr * 8;
        float vals[16];
        float m = -3.4e38f;
#pragma unroll
        for (int j = 0; j < 16; j++) {
            vals[j] = Ss[p * CHUNK_ + lane + 32 * j];
            m = fmaxf(m, vals[j]);
        }
#pragma unroll
        for (int o = 16; o > 0; o >>= 1) m = fmaxf(m, __shfl_xor_sync(0xffffffffu, m, o));
        float s = 0.f;
#pragma unroll
        for (int j = 0; j < 16; j++) {
            float e = expf(vals[j] - m);
            Ss[p * CHUNK_ + lane + 32 * j] = e;
            s += e;
        }
#pragma unroll
        for (int o = 16; o > 0; o >>= 1) s += __shfl_xor_sync(0xffffffffu, s, o);
        if (lane == 0) { Ms[p] = m; Ls[p] = s; }
    }

    int pg = tid >> 6;
    int d2 = tid & 63;
    float2 acc6[6];
#pragma unroll
    for (int j = 0; j < 6; j++) acc6[j] = make_float2(0.f, 0.f);
    const float2* Vs2 = (const float2*)Vs;
#pragma unroll 1
    for (int st = 0; st < 8; ++st) {
        __syncthreads();
#pragma unroll
        for (int j = 0; j < 8; j++) {
            int lin = tid + 256 * j;
            int row = lin >> 5, c4 = lin & 31;
            float4 vv = *(const float4*)&g_V[((size_t)(b * T_ + cz * CHUNK_ + st * 64 + row)) * D_ + h * HD_ + c4 * 4];
            *(float4*)&Vs[row * HD_ + c4 * 4] = vv;
        }
        __syncthreads();
#pragma unroll 4
        for (int tt0 = 0; tt0 < 64; tt0++) {
            float2 v = Vs2[tt0 * 64 + d2];
            int tt = st * 64 + tt0;
#pragma unroll
            for (int j = 0; j < 6; j++) {
                float sv = Ss[(pg * 6 + j) * CHUNK_ + tt];
                acc6[j].x += sv * v.x;
                acc6[j].y += sv * v.y;
            }
        }
    }
    size_t pb = ((((size_t)b * H_ + h) * NC_ + cz) * P_) * 130;
#pragma unroll
    for (int j = 0; j < 6; j++) {
        int p = pg * 6 + j;
        float* dst = g_part + pb + (size_t)p * 130;
        *(float2*)&dst[2 + 2 * d2] = acc6[j];
        if (d2 == 0) { dst[0] = Ms[p]; dst[1] = Ls[p]; }
    }
}

// ---------------- 5. merge ----------------
__global__ __launch_bounds__(128) void merge_kernel() {
    int p = blockIdx.x, h = blockIdx.y, b = blockIdx.z;
    int d = threadIdx.x;
    float M = -3.4e38f;
    for (int c = 0; c < NC_; c++) {
        const float* pp = g_part + (((size_t)(b * H_ + h) * NC_ + c) * P_ + p) * 130;
        M = fmaxf(M, pp[0]);
    }
    float L = 0.f, val = 0.f;
    for (int c = 0; c < NC_; c++) {
        const float* pp = g_part + (((size_t)(b * H_ + h) * NC_ + c) * P_ + p) * 130;
        float wgt = expf(pp[0] - M);
        L   += pp[1] * wgt;
        val += pp[2 + d] * wgt;
    }
    float out = (L > 0.f) ? val / L : 0.f;
    g_pt[(b * P_ + p) * D_ + h * HD_ + d] = out;
}

// ---------------- 6. topk ----------------
__global__ __launch_bounds__(256) void topk_kernel() {
    int b = blockIdx.x, tid = threadIdx.x, w = tid >> 5, lane = tid & 31;
    __shared__ float ss[P_];
    __shared__ int idxs[TOPK_];
#pragma unroll 1
    for (int rr = 0; rr < 3; rr++) {
        int p = w + rr * 8;
        const float* pr = g_pt + (b * P_ + p) * D_;
        float sq = 0.f;
#pragma unroll
        for (int j = 0; j < 16; j++) { float tv = pr[lane + 32 * j]; sq += tv * tv; }
#pragma unroll
        for (int o = 16; o > 0; o >>= 1) sq += __shfl_xor_sync(0xffffffffu, sq, o);
        if (lane == 0) ss[p] = sq;
    }
    __syncthreads();
    if (tid == 0) {
        unsigned used = 0;
        for (int i = 0; i < TOPK_; i++) {
            int best = -1; float bv = -3.4e38f;
            for (int p = 0; p < P_; p++)
                if (!((used >> p) & 1) && ss[p] > bv) { bv = ss[p]; best = p; }
            used |= 1u << best;
            idxs[i] = best;
        }
    }
    __syncthreads();
    for (int d = tid; d < D_; d += 256) {
        float s = 0.f;
        for (int i = 0; i < TOPK_; i++) s += g_pt[(b * P_ + idxs[i]) * D_ + d];
        g_z[b * D_ + d] = s * (1.f / TOPK_);
    }
}

// ---------------- 7. MLP ----------------
__global__ __launch_bounds__(128) void mlp_kernel(int in_sel, const float* __restrict__ W,
                                                  const float* __restrict__ bias,
                                                  float* __restrict__ out_ext, int act) {
    __shared__ float zs[D_];
    int b = blockIdx.y, tid = threadIdx.x;
    int n = blockIdx.x * 128 + tid;
    const float* in = in_sel ? g_hid : g_z;
    for (int i = tid; i < D_; i += 128) zs[i] = in[b * D_ + i];
    __syncthreads();
    const float* wr = W + (size_t)n * D_;
    float s = bias[n];
    for (int k = 0; k < D_; k += 4) {
        float4 w4 = *(const float4*)&wr[k];
        s += w4.x * zs[k] + w4.y * zs[k + 1] + w4.z * zs[k + 2] + w4.w * zs[k + 3];
    }
    if (act) s = s / (1.f + expf(-s));
    float* out = out_ext ? out_ext : g_hid;
    out[b * D_ + n] = s;
}

// ---------------- launch ----------------
extern "C" void kernel_launch(void* const* d_in, const int* in_sizes, int n_in,
                              void* d_out, int out_size) {
    (void)in_sizes; (void)n_in; (void)out_size;
    const float* x     = (const float*)d_in[0];
    const float* proto = (const float*)d_in[1];
    const float* ln_g  = (const float*)d_in[2];
    const float* ln_b  = (const float*)d_in[3];
    const float* Wq    = (const float*)d_in[4];
    const float* Wk    = (const float*)d_in[5];
    const float* Wv    = (const float*)d_in[6];
    const float* W1    = (const float*)d_in[7];
    const float* b1    = (const float*)d_in[8];
    const float* W2    = (const float*)d_in[9];
    const float* b2    = (const float*)d_in[10];
    float* out = (float*)d_out;

    const int gemm_smem = 4 * BUF_FLOATS * 4;   // 73728 bytes
    cudaFuncSetAttribute(gemm_mma, cudaFuncAttributeMaxDynamicSharedMemorySize, gemm_smem);
    cudaFuncSetAttribute(att_kernel, cudaFuncAttributeMaxDynamicSharedMemorySize, 94400);

    ln_kernel<<<(B_ * T_) / 8, 256>>>(x, ln_g, ln_b);
    round_w<<<(D_ * D_) / 256, 256>>>(Wk, Wv);
    gemm_mma<<<dim3(8, 512), 256, gemm_smem>>>();
    qh_kernel<<<P_, 512>>>(proto, Wq);
    att_kernel<<<dim3(NC_, H_, B_), 256, 94400>>>();
    merge_kernel<<<dim3(P_, H_, B_), 128>>>();
    topk_kernel<<<B_, 256>>>();
    mlp_kernel<<<dim3(4, B_), 128>>>(0, W1, b1, nullptr, 1);
    mlp_kernel<<<dim3(4, B_), 128>>>(1, W2, b2, out, 0);
}